// round 10
// baseline (speedup 1.0000x reference)
#include <cuda_runtime.h>
#include <cuda_bf16.h>
#include <math.h>

#define NMAX 30000
#define EMAX 600000

// ---------------- scratch (static device globals; no allocation) ----------------
__device__ float         d_xp  [NMAX * 256];   // xp; later Y2 in mma path
__device__ float         d_agg [NMAX * 256];   // x_local0 (incl conv_b) -> final x_local
__device__ float         d_y1  [NMAX * 256];   // Y1 = lrelu(fc(x0)+b)
__device__ float         d_x2  [NMAX * 256];   // x2
__device__ float         d_asrc[NMAX * 8];
__device__ float         d_adst[NMAX * 8];
__device__ float         d_fcT [256 * 256];    // fc_w transposed [k][o] (fallback)
__device__ __nv_bfloat16 d_fcBhi[256 * 256];   // fc_w bf16 hi/lo, [n][k] native layout
__device__ __nv_bfloat16 d_fcBlo[256 * 256];
__device__ float         d_gate[NMAX];
__device__ float         d_gsum;
__device__ float         d_xglob[256];
__device__ float         d_ga[256];
__device__ int           d_ok;
// CSR build
__device__ int           d_cnt[NMAX + 1];
__device__ int           d_cur[NMAX];
__device__ int           d_srcs[EMAX];
__device__ int           d_bsum[64];

// ---------------- helpers ----------------
__device__ __forceinline__ float lrelu(float x, float s) { return x > 0.f ? x : s * x; }

__device__ __forceinline__ float wredsum(float v) {
    #pragma unroll
    for (int s = 16; s; s >>= 1) v += __shfl_xor_sync(0xffffffffu, v, s);
    return v;
}
__device__ __forceinline__ float wredmax(float v) {
    #pragma unroll
    for (int s = 16; s; s >>= 1) v = fmaxf(v, __shfl_xor_sync(0xffffffffu, v, s));
    return v;
}

__device__ __forceinline__ void split_bf16(float x, __nv_bfloat16& hi, __nv_bfloat16& lo) {
    hi = __float2bfloat16(x);
    lo = __float2bfloat16(x - __bfloat162float(hi));
}

__device__ __forceinline__ void mma16(float* c, const unsigned* a, unsigned b0, unsigned b1) {
    asm volatile(
        "mma.sync.aligned.m16n8k16.row.col.f32.bf16.bf16.f32 "
        "{%0,%1,%2,%3},{%4,%5,%6,%7},{%8,%9},{%0,%1,%2,%3};"
        : "+f"(c[0]), "+f"(c[1]), "+f"(c[2]), "+f"(c[3])
        : "r"(a[0]), "r"(a[1]), "r"(a[2]), "r"(a[3]), "r"(b0), "r"(b1));
}

// block reduce of 16 per-thread values over 256 threads (fallback k_dense)
__device__ __forceinline__ void reduce16(const float* v, float* sred, float* out,
                                         bool ismax, int tid) {
    int wid = tid >> 5, lane = tid & 31;
    #pragma unroll
    for (int m = 0; m < 16; m++) {
        float r = ismax ? wredmax(v[m]) : wredsum(v[m]);
        if (lane == 0) sred[m * 8 + wid] = r;
    }
    __syncthreads();
    if (tid < 16) {
        float r = sred[tid * 8];
        #pragma unroll
        for (int j = 1; j < 8; j++) {
            float t = sred[tid * 8 + j];
            r = ismax ? fmaxf(r, t) : r + t;
        }
        out[tid] = r;
    }
    __syncthreads();
}

// ---------------- setup ----------------
__global__ void k_init(int n) {
    int idx = blockIdx.x * blockDim.x + threadIdx.x;
    if (idx <= n) d_cnt[idx] = 0;
    if (idx < 256) d_xglob[idx] = 0.f;
    if (idx == 0) d_gsum = 0.f;
}

__global__ void k_fcT(const float* __restrict__ fc) {
    int idx = blockIdx.x * blockDim.x + threadIdx.x;  // 65536
    int o = idx >> 8, k = idx & 255;
    d_fcT[k * 256 + o] = fc[idx];
    __nv_bfloat16 hi, lo;
    split_bf16(fc[idx], hi, lo);
    d_fcBhi[idx] = hi;  // [n][k] native layout
    d_fcBlo[idx] = lo;
}

// ---------------- CSR build ----------------
__global__ void k_hist(const int* __restrict__ ei, int E) {
    int e = blockIdx.x * blockDim.x + threadIdx.x;
    if (e < E) atomicAdd(&d_cnt[ei[E + e]], 1);
}

__global__ void k_scan1(int n) {
    __shared__ int sh[1024];
    int b = blockIdx.x, t = threadIdx.x;
    int i = b * 1024 + t;
    int v = (i < n) ? d_cnt[i] : 0;
    sh[t] = v;
    __syncthreads();
    #pragma unroll
    for (int off = 1; off < 1024; off <<= 1) {
        int x = (t >= off) ? sh[t - off] : 0;
        __syncthreads();
        sh[t] += x;
        __syncthreads();
    }
    if (i < n) d_cur[i] = sh[t] - v;
    if (t == 1023) d_bsum[b] = sh[1023];
}

__global__ void k_scan2(int nb) {
    int t = threadIdx.x;
    int v = (t < nb) ? d_bsum[t] : 0;
    int orig = v;
    #pragma unroll
    for (int off = 1; off < 32; off <<= 1) {
        int x = __shfl_up_sync(0xffffffffu, v, off);
        if (t >= off) v += x;
    }
    if (t < nb) d_bsum[t] = v - orig;
}

__global__ void k_scan3(int n, int E) {
    int b = blockIdx.x, t = threadIdx.x;
    int i = b * 1024 + t;
    if (i < n) {
        int v = d_cur[i] + d_bsum[b];
        d_cnt[i] = v;
        d_cur[i] = v;
    }
    if (i == 0) d_cnt[n] = E;
}

__global__ void k_scatter(const int* __restrict__ ei, int E) {
    int e = blockIdx.x * blockDim.x + threadIdx.x;
    if (e >= E) return;
    int d = ei[E + e];
    int pos = atomicAdd(&d_cur[d], 1);
    d_srcs[pos] = ei[e];
}

// ---------------- xp + alpha (proven) ----------------
__global__ void __launch_bounds__(256)
k_xp(const float* __restrict__ x, const float* __restrict__ W,
     const float* __restrict__ a_src, const float* __restrict__ a_dst, int n) {
    __shared__ float xs[8][128];
    int tid = threadIdx.x;
    int n0 = blockIdx.x * 8;
    for (int idx = tid; idx < 8 * 128; idx += 256) {
        int m = idx >> 7, i = idx & 127;
        int nn = n0 + m;
        xs[m][i] = (nn < n) ? x[(size_t)nn * 128 + i] : 0.f;
    }
    __syncthreads();

    int h = tid >> 5, d = tid & 31;
    const float* Wp = W + (size_t)h * 4096 + d;
    float acc[8];
    #pragma unroll
    for (int m = 0; m < 8; m++) acc[m] = 0.f;
    #pragma unroll 1
    for (int i4 = 0; i4 < 32; i4++) {
        float w0 = Wp[(i4 * 4 + 0) * 32];
        float w1 = Wp[(i4 * 4 + 1) * 32];
        float w2 = Wp[(i4 * 4 + 2) * 32];
        float w3 = Wp[(i4 * 4 + 3) * 32];
        #pragma unroll
        for (int m = 0; m < 8; m++) {
            float4 xv = ((const float4*)xs[m])[i4];
            acc[m] = fmaf(xv.x, w0, acc[m]);
            acc[m] = fmaf(xv.y, w1, acc[m]);
            acc[m] = fmaf(xv.z, w2, acc[m]);
            acc[m] = fmaf(xv.w, w3, acc[m]);
        }
    }

    float asv = a_src[h * 32 + d];
    float adv = a_dst[h * 32 + d];
    int lane = tid & 31;
    #pragma unroll
    for (int m = 0; m < 8; m++) {
        int nn = n0 + m;
        float rs = wredsum(acc[m] * asv);
        float rd = wredsum(acc[m] * adv);
        if (nn < n) {
            d_xp[(size_t)nn * 256 + tid] = acc[m];
            if (lane == 0) {
                d_asrc[nn * 8 + h] = rs;
                d_adst[nn * 8 + h] = rd;
            }
        }
    }
}

// ---------------- fused attention aggregation (+conv_b) ----------------
__global__ void __launch_bounds__(256)
k_agg(const float* __restrict__ conv_b, int n) {
    int warp = threadIdx.x >> 5;
    int lane = threadIdx.x & 31;
    int d = blockIdx.x * 8 + warp;
    if (d >= n) return;

    int beg = d_cnt[d], end = d_cnt[d + 1];
    float adstv = (lane < 8) ? d_adst[d * 8 + lane] : 0.f;

    float esum = 0.f;
    float acc[8];
    #pragma unroll
    for (int j = 0; j < 8; j++) acc[j] = 0.f;

    int s = d;
    int p = beg - 1;
    while (true) {
        float av = 0.f;
        if (lane < 8) {
            float lg = lrelu(d_asrc[s * 8 + lane] + adstv, 0.2f);
            av = __expf(lg);
            esum += av;
        }
        const float* xr = d_xp + (size_t)s * 256;
        #pragma unroll
        for (int j = 0; j < 8; j++) {
            float ah = __shfl_sync(0xffffffffu, av, j);
            acc[j] = fmaf(ah, xr[j * 32 + lane], acc[j]);
        }
        p++;
        if (p >= end) break;
        s = d_srcs[p];
    }

    float* outr = d_agg + (size_t)d * 256;
    #pragma unroll
    for (int j = 0; j < 8; j++) {
        float sh = __shfl_sync(0xffffffffu, esum, j);
        outr[j * 32 + lane] = acc[j] / (sh + 1e-16f) + conv_b[j * 32 + lane];
    }
}

// ---------------- bf16x3-split GEMM: C[M,256] = A[M,K] @ Bt^T (Bt is [n][k])
template<int ACT, int GUARDED>
__global__ void __launch_bounds__(256)
k_gemm(const float* __restrict__ A,
       const __nv_bfloat16* __restrict__ Bthi,
       const __nv_bfloat16* __restrict__ Btlo,
       const float* __restrict__ bias,
       float* __restrict__ Cmat, int M, int K) {
    if (GUARDED && d_ok == 0) return;
    __shared__ __nv_bfloat16 As_hi[128][24], As_lo[128][24];  // [row][k]
    __shared__ __nv_bfloat16 Bs_hi[128][24], Bs_lo[128][24];  // [col][k]
    int t = threadIdx.x;
    int mBase = blockIdx.x * 128, nBase = blockIdx.y * 128;
    int lane = t & 31, wid = t >> 5;
    int wm = (wid & 3) * 32, wn = (wid >> 2) * 64;
    int g = lane >> 2, tg = lane & 3;

    float c[2][8][4];
    #pragma unroll
    for (int mt = 0; mt < 2; mt++)
        #pragma unroll
        for (int nt = 0; nt < 8; nt++)
            #pragma unroll
            for (int q = 0; q < 4; q++) c[mt][nt][q] = 0.f;

    int arow = t >> 1, ahalf = (t & 1) * 8;
    int bcol = t >> 1, bhalf = (t & 1) * 8;

    for (int k0 = 0; k0 < K; k0 += 16) {
        {
            int gm = mBase + arow;
            #pragma unroll
            for (int q = 0; q < 2; q++) {
                int kk = ahalf + q * 4;
                float4 v = make_float4(0.f, 0.f, 0.f, 0.f);
                if (gm < M) v = *(const float4*)(A + (size_t)gm * K + k0 + kk);
                __nv_bfloat16 hx, lx, hy, ly, hz, lz, hw, lw;
                split_bf16(v.x, hx, lx);
                split_bf16(v.y, hy, ly);
                split_bf16(v.z, hz, lz);
                split_bf16(v.w, hw, lw);
                __nv_bfloat162 p;
                p.x = hx; p.y = hy; *(__nv_bfloat162*)&As_hi[arow][kk]     = p;
                p.x = hz; p.y = hw; *(__nv_bfloat162*)&As_hi[arow][kk + 2] = p;
                p.x = lx; p.y = ly; *(__nv_bfloat162*)&As_lo[arow][kk]     = p;
                p.x = lz; p.y = lw; *(__nv_bfloat162*)&As_lo[arow][kk + 2] = p;
            }
        }
        {
            const __nv_bfloat16* sh = Bthi + (size_t)(nBase + bcol) * K + k0 + bhalf;
            const __nv_bfloat16* sl = Btlo + (size_t)(nBase + bcol) * K + k0 + bhalf;
            *(uint4*)&Bs_hi[bcol][bhalf] = *(const uint4*)sh;
            *(uint4*)&Bs_lo[bcol][bhalf] = *(const uint4*)sl;
        }
        __syncthreads();

        unsigned ahi[2][4], alo[2][4];
        #pragma unroll
        for (int mt = 0; mt < 2; mt++) {
            int rm = wm + mt * 16 + g;
            ahi[mt][0] = *(const unsigned*)&As_hi[rm][tg * 2];
            ahi[mt][1] = *(const unsigned*)&As_hi[rm + 8][tg * 2];
            ahi[mt][2] = *(const unsigned*)&As_hi[rm][tg * 2 + 8];
            ahi[mt][3] = *(const unsigned*)&As_hi[rm + 8][tg * 2 + 8];
            alo[mt][0] = *(const unsigned*)&As_lo[rm][tg * 2];
            alo[mt][1] = *(const unsigned*)&As_lo[rm + 8][tg * 2];
            alo[mt][2] = *(const unsigned*)&As_lo[rm][tg * 2 + 8];
            alo[mt][3] = *(const unsigned*)&As_lo[rm + 8][tg * 2 + 8];
        }
        #pragma unroll
        for (int nt = 0; nt < 8; nt++) {
            int cn = wn + nt * 8 + g;
            unsigned bh0 = *(const unsigned*)&Bs_hi[cn][tg * 2];
            unsigned bh1 = *(const unsigned*)&Bs_hi[cn][tg * 2 + 8];
            unsigned bl0 = *(const unsigned*)&Bs_lo[cn][tg * 2];
            unsigned bl1 = *(const unsigned*)&Bs_lo[cn][tg * 2 + 8];
            #pragma unroll
            for (int mt = 0; mt < 2; mt++) {
                mma16(c[mt][nt], ahi[mt], bh0, bh1);
                mma16(c[mt][nt], ahi[mt], bl0, bl1);
                mma16(c[mt][nt], alo[mt], bh0, bh1);
            }
        }
        __syncthreads();
    }
    #pragma unroll
    for (int mt = 0; mt < 2; mt++) {
        int row0 = mBase + wm + mt * 16 + g;
        #pragma unroll
        for (int nt = 0; nt < 8; nt++) {
            int col = nBase + wn + nt * 8 + tg * 2;
            float b0 = bias ? bias[col] : 0.f;
            float b1 = bias ? bias[col + 1] : 0.f;
            float v0 = c[mt][nt][0] + b0, v1 = c[mt][nt][1] + b1;
            float v2 = c[mt][nt][2] + b0, v3 = c[mt][nt][3] + b1;
            if (ACT) {
                v0 = lrelu(v0, 0.01f); v1 = lrelu(v1, 0.01f);
                v2 = lrelu(v2, 0.01f); v3 = lrelu(v3, 0.01f);
            }
            if (row0 < M) { float2 w = {v0, v1}; *(float2*)(Cmat + (size_t)row0 * 256 + col) = w; }
            if (row0 + 8 < M) { float2 w = {v2, v3}; *(float2*)(Cmat + (size_t)(row0 + 8) * 256 + col) = w; }
        }
    }
}

// verify mma GEMM row 0 against fp32 FFMA; sets d_ok
__global__ void k_check(const float* __restrict__ fc_w, const float* __restrict__ fc_b) {
    __shared__ int bad;
    int t = threadIdx.x;
    if (t == 0) bad = 0;
    __syncthreads();
    float acc = fc_b[t];
    const float* a0 = d_agg;                 // row 0
    const float* wr = fc_w + (size_t)t * 256;
    for (int k = 0; k < 256; k++) acc = fmaf(a0[k], wr[k], acc);
    acc = lrelu(acc, 0.01f);
    float gv = d_y1[t];
    if (!isfinite(gv) || fabsf(gv - acc) > 0.05f * (fabsf(acc) + 0.1f)) atomicAdd(&bad, 1);
    __syncthreads();
    if (t == 0) d_ok = (bad <= 16) ? 1 : 0;
}

// row softmax of Y1 + x2 = lrelu(x0 * sa, 0.2). one warp per row. [mma path]
__global__ void __launch_bounds__(256)
k_soft(int n) {
    if (d_ok == 0) return;
    int wid = threadIdx.x >> 5, lane = threadIdx.x & 31;
    int nd = blockIdx.x * 8 + wid;
    if (nd >= n) return;
    const float* yr = d_y1 + (size_t)nd * 256;
    const float* x0 = d_agg + (size_t)nd * 256;
    float* o = d_x2 + (size_t)nd * 256;
    float v[8];
    float mx = -1e30f;
    #pragma unroll
    for (int j = 0; j < 8; j++) { v[j] = yr[j * 32 + lane]; mx = fmaxf(mx, v[j]); }
    mx = wredmax(mx);
    float sum = 0.f;
    #pragma unroll
    for (int j = 0; j < 8; j++) { v[j] = __expf(v[j] - mx); sum += v[j]; }
    sum = wredsum(sum);
    float inv = 1.f / sum;
    #pragma unroll
    for (int j = 0; j < 8; j++)
        o[j * 32 + lane] = lrelu(x0[j * 32 + lane] * (v[j] * inv), 0.2f);
}

// LayerNorm + L2 normalize + gate on Y2 (d_xp) -> d_agg, d_gate. [mma path]
__global__ void __launch_bounds__(256)
k_norm(const float* __restrict__ ln_w, const float* __restrict__ ln_b,
       const float* __restrict__ gw, const float* __restrict__ gb, int n) {
    if (d_ok == 0) return;
    int wid = threadIdx.x >> 5, lane = threadIdx.x & 31;
    int nd = blockIdx.x * 8 + wid;
    if (nd >= n) return;
    const float* yr = d_xp + (size_t)nd * 256;
    float* o = d_agg + (size_t)nd * 256;
    float v[8];
    float sum = 0.f;
    #pragma unroll
    for (int j = 0; j < 8; j++) { v[j] = yr[j * 32 + lane]; sum += v[j]; }
    sum = wredsum(sum);
    float mu = sum * (1.f / 256.f);
    float sq = 0.f;
    #pragma unroll
    for (int j = 0; j < 8; j++) { float dd = v[j] - mu; sq += dd * dd; }
    sq = wredsum(sq);
    float rstd = rsqrtf(sq * (1.f / 256.f) + 1e-5f);
    float s2 = 0.f;
    #pragma unroll
    for (int j = 0; j < 8; j++) {
        v[j] = (v[j] - mu) * rstd * ln_w[j * 32 + lane] + ln_b[j * 32 + lane];
        s2 += v[j] * v[j];
    }
    s2 = wredsum(s2);
    float invn = 1.f / fmaxf(sqrtf(s2), 1e-12f);
    float gacc = 0.f;
    #pragma unroll
    for (int j = 0; j < 8; j++) {
        v[j] *= invn;
        o[j * 32 + lane] = v[j];
        gacc += v[j] * gw[j * 32 + lane];
    }
    gacc = wredsum(gacc);
    if (lane == 0) d_gate[nd] = gacc + gb[0];
}

// -------- fallback dense chain (round-7 proven; conv_b already in d_agg) --------
__global__ void __launch_bounds__(256)
k_dense_fb(const float* __restrict__ fc_b,
           const float* __restrict__ ln_w, const float* __restrict__ ln_b,
           const float* __restrict__ gw, const float* __restrict__ gb, int n) {
    if (d_ok != 0) return;
    __shared__ float vs[16][256];
    __shared__ float sred[16 * 8];
    __shared__ float sbc[16];
    __shared__ float sbc2[16];
    int tid = threadIdx.x;
    int n0 = blockIdx.x * 16;
    float fb = fc_b[tid];
    float lw = ln_w[tid], lb = ln_b[tid];

    #pragma unroll
    for (int m = 0; m < 16; m++) {
        int nn = n0 + m;
        vs[m][tid] = (nn < n) ? d_agg[(size_t)nn * 256 + tid] : 0.f;
    }
    __syncthreads();

    float acc[16];
    #pragma unroll
    for (int m = 0; m < 16; m++) acc[m] = fb;
    #pragma unroll 1
    for (int k4 = 0; k4 < 64; k4++) {
        const float* wp = &d_fcT[k4 * 4 * 256 + tid];
        float w0 = wp[0], w1 = wp[256], w2 = wp[512], w3 = wp[768];
        #pragma unroll
        for (int m = 0; m < 16; m++) {
            float4 v = ((const float4*)vs[m])[k4];
            acc[m] = fmaf(v.x, w0, acc[m]);
            acc[m] = fmaf(v.y, w1, acc[m]);
            acc[m] = fmaf(v.z, w2, acc[m]);
            acc[m] = fmaf(v.w, w3, acc[m]);
        }
    }
    #pragma unroll
    for (int m = 0; m < 16; m++) acc[m] = lrelu(acc[m], 0.01f);

    reduce16(acc, sred, sbc, true, tid);
    float e[16];
    #pragma unroll
    for (int m = 0; m < 16; m++) e[m] = __expf(acc[m] - sbc[m]);
    reduce16(e, sred, sbc2, false, tid);

    float x2[16];
    #pragma unroll
    for (int m = 0; m < 16; m++) {
        float sa = e[m] / sbc2[m];
        x2[m] = lrelu(vs[m][tid] * sa, 0.2f);
    }
    __syncthreads();
    #pragma unroll
    for (int m = 0; m < 16; m++) vs[m][tid] = x2[m];
    __syncthreads();

    #pragma unroll
    for (int m = 0; m < 16; m++) acc[m] = fb;
    #pragma unroll 1
    for (int k4 = 0; k4 < 64; k4++) {
        const float* wp = &d_fcT[k4 * 4 * 256 + tid];
        float w0 = wp[0], w1 = wp[256], w2 = wp[512], w3 = wp[768];
        #pragma unroll
        for (int m = 0; m < 16; m++) {
            float4 v = ((const float4*)vs[m])[k4];
            acc[m] = fmaf(v.x, w0, acc[m]);
            acc[m] = fmaf(v.y, w1, acc[m]);
            acc[m] = fmaf(v.z, w2, acc[m]);
            acc[m] = fmaf(v.w, w3, acc[m]);
        }
    }

    reduce16(acc, sred, sbc, false, tid);
    float mu[16], sq[16];
    #pragma unroll
    for (int m = 0; m < 16; m++) {
        mu[m] = sbc[m] * (1.f / 256.f);
        float dd = acc[m] - mu[m];
        sq[m] = dd * dd;
    }
    reduce16(sq, sred, sbc2, false, tid);
    float xl[16];
    #pragma unroll
    for (int m = 0; m < 16; m++) {
        float var = sbc2[m] * (1.f / 256.f);
        xl[m] = (acc[m] - mu[m]) * rsqrtf(var + 1e-5f) * lw + lb;
    }

    #pragma unroll
    for (int m = 0; m < 16; m++) sq[m] = xl[m] * xl[m];
    reduce16(sq, sred, sbc, false, tid);
    #pragma unroll
    for (int m = 0; m < 16; m++) xl[m] /= fmaxf(sqrtf(sbc[m]), 1e-12f);

    float gwt = gw[tid];
    #pragma unroll
    for (int m = 0; m < 16; m++) sq[m] = xl[m] * gwt;
    reduce16(sq, sred, sbc2, false, tid);
    if (tid < 16 && n0 + tid < n) d_gate[n0 + tid] = sbc2[tid] + gb[0];

    #pragma unroll
    for (int m = 0; m < 16; m++)
        if (n0 + m < n) d_agg[(size_t)(n0 + m) * 256 + tid] = xl[m];
}

// ---------------- pooling / output ----------------
__global__ void k_gpool(int n) {
    __shared__ float en[256];
    __shared__ float r8[8];
    int tid = threadIdx.x;
    int n0 = blockIdx.x * 256;
    int nn = n0 + tid;
    float ev = (nn < n) ? __expf(d_gate[nn]) : 0.f;
    en[tid] = ev;
    float r = wredsum(ev);
    if ((tid & 31) == 0) r8[tid >> 5] = r;
    __syncthreads();
    if (tid == 0) {
        float s = 0.f;
        #pragma unroll
        for (int j = 0; j < 8; j++) s += r8[j];
        atomicAdd(&d_gsum, s);
    }
    float part = 0.f;
    int lim = min(256, n - n0);
    for (int i = 0; i < lim; i++)
        part += en[i] * d_agg[(size_t)(n0 + i) * 256 + tid];
    atomicAdd(&d_xglob[tid], part);
}

__global__ void k_ga(const float* __restrict__ gfcw, const float* __restrict__ gfcb) {
    __shared__ float xg[256];
    __shared__ float r8[8];
    __shared__ float bres;
    int tid = threadIdx.x;
    xg[tid] = d_xglob[tid] / (d_gsum + 1e-16f);
    __syncthreads();
    float acc = gfcb[tid];
    const float* row = gfcw + (size_t)tid * 256;
    #pragma unroll 4
    for (int k = 0; k < 256; k++) acc += xg[k] * row[k];
    acc = fmaxf(acc, 0.f);
    float r = wredmax(acc);
    if ((tid & 31) == 0) r8[tid >> 5] = r;
    __syncthreads();
    if (tid == 0) {
        float m = r8[0];
        #pragma unroll
        for (int j = 1; j < 8; j++) m = fmaxf(m, r8[j]);
        bres = m;
    }
    __syncthreads();
    float e = __expf(acc - bres);
    r = wredsum(e);
    if ((tid & 31) == 0) r8[tid >> 5] = r;
    __syncthreads();
    if (tid == 0) {
        float s = 0.f;
        #pragma unroll
        for (int j = 0; j < 8; j++) s += r8[j];
        bres = s;
    }
    __syncthreads();
    d_ga[tid] = e / bres;
}

__global__ void k_out(float* __restrict__ out, int n) {
    int idx = blockIdx.x * blockDim.x + threadIdx.x;
    if (idx >= n * 64) return;
    int o4 = idx & 63;
    float4 g = ((const float4*)d_ga)[o4];
    float4 v = ((const float4*)d_agg)[idx];
    v.x *= g.x; v.y *= g.y; v.z *= g.z; v.w *= g.w;
    ((float4*)out)[idx] = v;
}

// ---------------- launch ----------------
extern "C" void kernel_launch(void* const* d_in, const int* in_sizes, int n_in,
                              void* d_out, int out_size) {
    const float* x      = (const float*)d_in[0];
    const int*   ei     = (const int*)  d_in[1];
    const float* W      = (const float*)d_in[4];
    const float* a_src  = (const float*)d_in[5];
    const float* a_dst  = (const float*)d_in[6];
    const float* conv_b = (const float*)d_in[7];
    const float* fc_w   = (const float*)d_in[8];
    const float* fc_b   = (const float*)d_in[9];
    const float* ln_w   = (const float*)d_in[10];
    const float* ln_b   = (const float*)d_in[11];
    const float* gate_w = (const float*)d_in[12];
    const float* gate_b = (const float*)d_in[13];
    const float* gfc_w  = (const float*)d_in[14];
    const float* gfc_b  = (const float*)d_in[15];
    float* out = (float*)d_out;

    int n = in_sizes[0] / 128;
    int E = in_sizes[1] / 2;
    int nb = (n + 1023) / 1024;
    int mT = (n + 127) / 128;

    k_init<<<(n + 256) / 256, 256>>>(n);
    k_fcT<<<256, 256>>>(fc_w);
    k_hist<<<(E + 255) / 256, 256>>>(ei, E);
    k_scan1<<<nb, 1024>>>(n);
    k_scan2<<<1, 32>>>(nb);
    k_scan3<<<nb, 1024>>>(n, E);
    k_scatter<<<(E + 255) / 256, 256>>>(ei, E);
    k_xp<<<(n + 7) / 8, 256>>>(x, W, a_src, a_dst, n);
    k_agg<<<(n + 7) / 8, 256>>>(conv_b, n);
    // mma path: GEMM1 -> check -> (soft -> GEMM2 -> norm) if ok
    k_gemm<1, 0><<<dim3(mT, 2), 256>>>(d_agg, d_fcBhi, d_fcBlo, fc_b, d_y1, n, 256);
    k_check<<<1, 256>>>(fc_w, fc_b);
    k_soft<<<(n + 7) / 8, 256>>>(n);
    k_gemm<0, 1><<<dim3(mT, 2), 256>>>(d_x2, d_fcBhi, d_fcBlo, fc_b, d_xp, n, 256);
    k_norm<<<(n + 7) / 8, 256>>>(ln_w, ln_b, gate_w, gate_b, n);
    // fallback path (runs only if mma check failed)
    k_dense_fb<<<(n + 15) / 16, 256>>>(fc_b, ln_w, ln_b, gate_w, gate_b, n);
    k_gpool<<<(n + 255) / 256, 256>>>(n);
    k_ga<<<1, 256>>>(gfc_w, gfc_b);
    k_out<<<(n * 64 + 255) / 256, 256>>>(out, n);
}

// round 14
// speedup vs baseline: 3.1585x; 3.1585x over previous
#include <cuda_runtime.h>
#include <cuda_bf16.h>
#include <stdint.h>
#include <math.h>

#define NMAX 30000
#define EMAX 600000

// ---------------- scratch ----------------
__device__ float      d_xp  [NMAX * 256];
__device__ float      d_agg [NMAX * 256];
__device__ float      d_asrc[NMAX * 8];
__device__ float      d_adst[NMAX * 8];
__device__ ulonglong2 d_fcTp[64 * 256];    // fc_w^T packed: [k4][o] = 4 floats {w[4k4..4k4+3][o]}
__device__ ulonglong2 d_Wp  [8 * 32 * 32]; // W packed: [h][i4][d] = 4 floats {W[h][4i4..4i4+3][d]}
__device__ float      d_gsum;
__device__ float      d_xglob[256];
__device__ float      d_ga[256];
__device__ int        d_cnt[NMAX + 1];
__device__ int        d_cur[NMAX];
__device__ int        d_srcs[EMAX];
__device__ int        d_bsum[64];

// ---------------- helpers ----------------
__device__ __forceinline__ float lrelu(float x, float s) { return x > 0.f ? x : s * x; }

__device__ __forceinline__ float wredsum(float v) {
    #pragma unroll
    for (int s = 16; s; s >>= 1) v += __shfl_xor_sync(0xffffffffu, v, s);
    return v;
}
__device__ __forceinline__ float wredmax(float v) {
    #pragma unroll
    for (int s = 16; s; s >>= 1) v = fmaxf(v, __shfl_xor_sync(0xffffffffu, v, s));
    return v;
}

// packed f32x2 FMA: c = a*b + c (elementwise on two packed floats)
__device__ __forceinline__ void fma2(unsigned long long& c, unsigned long long a,
                                     unsigned long long b) {
    asm("fma.rn.f32x2 %0, %1, %2, %0;" : "+l"(c) : "l"(a), "l"(b));
}
__device__ __forceinline__ float unpack_sum(unsigned long long p) {
    float lo, hi;
    asm("mov.b64 {%0,%1}, %2;" : "=f"(lo), "=f"(hi) : "l"(p));
    return lo + hi;
}

// block reduce of 16 per-thread values over 256 threads
__device__ __forceinline__ void reduce16(const float* v, float* sred, float* out,
                                         bool ismax, int tid) {
    int wid = tid >> 5, lane = tid & 31;
    #pragma unroll
    for (int m = 0; m < 16; m++) {
        float r = ismax ? wredmax(v[m]) : wredsum(v[m]);
        if (lane == 0) sred[m * 8 + wid] = r;
    }
    __syncthreads();
    if (tid < 16) {
        float r = sred[tid * 8];
        #pragma unroll
        for (int j = 1; j < 8; j++) {
            float t = sred[tid * 8 + j];
            r = ismax ? fmaxf(r, t) : r + t;
        }
        out[tid] = r;
    }
    __syncthreads();
}

// ---------------- setup ----------------
__global__ void k_init(int n) {
    int idx = blockIdx.x * blockDim.x + threadIdx.x;
    if (idx <= n) d_cnt[idx] = 0;
    if (idx < 256) d_xglob[idx] = 0.f;
    if (idx == 0) d_gsum = 0.f;
}

__global__ void k_fcT(const float* __restrict__ fc) {
    int idx = blockIdx.x * blockDim.x + threadIdx.x;  // 65536; fc[o][k]
    int o = idx >> 8, k = idx & 255;
    ((float*)d_fcTp)[(k >> 2) * 1024 + o * 4 + (k & 3)] = fc[idx];
}

__global__ void k_wp(const float* __restrict__ W) {
    int idx = blockIdx.x * blockDim.x + threadIdx.x;  // 32768 = h*4096 + i*32 + d
    int h = idx >> 12, i = (idx >> 5) & 127, d = idx & 31;
    ((float*)d_Wp)[(((h * 32) + (i >> 2)) * 32 + d) * 4 + (i & 3)] = W[idx];
}

// ---------------- CSR build (proven) ----------------
__global__ void k_hist(const int* __restrict__ ei, int E) {
    int e = blockIdx.x * blockDim.x + threadIdx.x;
    if (e < E) atomicAdd(&d_cnt[ei[E + e]], 1);
}
__global__ void k_scan1(int n) {
    __shared__ int sh[1024];
    int b = blockIdx.x, t = threadIdx.x;
    int i = b * 1024 + t;
    int v = (i < n) ? d_cnt[i] : 0;
    sh[t] = v;
    __syncthreads();
    #pragma unroll
    for (int off = 1; off < 1024; off <<= 1) {
        int x = (t >= off) ? sh[t - off] : 0;
        __syncthreads();
        sh[t] += x;
        __syncthreads();
    }
    if (i < n) d_cur[i] = sh[t] - v;
    if (t == 1023) d_bsum[b] = sh[1023];
}
__global__ void k_scan2(int nb) {
    int t = threadIdx.x;
    int v = (t < nb) ? d_bsum[t] : 0;
    int orig = v;
    #pragma unroll
    for (int off = 1; off < 32; off <<= 1) {
        int x = __shfl_up_sync(0xffffffffu, v, off);
        if (t >= off) v += x;
    }
    if (t < nb) d_bsum[t] = v - orig;
}
__global__ void k_scan3(int n, int E) {
    int b = blockIdx.x, t = threadIdx.x;
    int i = b * 1024 + t;
    if (i < n) {
        int v = d_cur[i] + d_bsum[b];
        d_cnt[i] = v;
        d_cur[i] = v;
    }
    if (i == 0) d_cnt[n] = E;
}
__global__ void k_scatter(const int* __restrict__ ei, int E) {
    int e = blockIdx.x * blockDim.x + threadIdx.x;
    if (e >= E) return;
    int d = ei[E + e];
    int pos = atomicAdd(&d_cur[d], 1);
    d_srcs[pos] = ei[e];
}

// ---------------- xp + alpha (f32x2 inner loop) ----------------
__global__ void __launch_bounds__(256)
k_xp(const float* __restrict__ x,
     const float* __restrict__ a_src, const float* __restrict__ a_dst, int n) {
    __shared__ __align__(16) float xs[8][128];
    int tid = threadIdx.x;
    int n0 = blockIdx.x * 8;
    for (int idx = tid; idx < 8 * 128; idx += 256) {
        int m = idx >> 7, i = idx & 127;
        int nn = n0 + m;
        xs[m][i] = (nn < n) ? x[(size_t)nn * 128 + i] : 0.f;
    }
    __syncthreads();

    int h = tid >> 5, d = tid & 31;
    unsigned long long acc2[8];
    #pragma unroll
    for (int m = 0; m < 8; m++) acc2[m] = 0ull;
    const ulonglong2* Wp = d_Wp + (size_t)h * 32 * 32 + d;   // [i4][d], stride 32
    #pragma unroll 1
    for (int i4 = 0; i4 < 32; i4++) {
        ulonglong2 wv = Wp[i4 * 32];
        #pragma unroll
        for (int m = 0; m < 8; m++) {
            ulonglong2 xv = ((const ulonglong2*)xs[m])[i4];
            fma2(acc2[m], xv.x, wv.x);
            fma2(acc2[m], xv.y, wv.y);
        }
    }

    float asv = a_src[h * 32 + d];
    float adv = a_dst[h * 32 + d];
    int lane = tid & 31;
    #pragma unroll
    for (int m = 0; m < 8; m++) {
        float acc = unpack_sum(acc2[m]);
        int nn = n0 + m;
        float rs = wredsum(acc * asv);
        float rd = wredsum(acc * adv);
        if (nn < n) {
            d_xp[(size_t)nn * 256 + tid] = acc;
            if (lane == 0) {
                d_asrc[nn * 8 + h] = rs;
                d_adst[nn * 8 + h] = rd;
            }
        }
    }
}

// ---------------- fused attention aggregation (+conv_b) — proven ----------------
__global__ void __launch_bounds__(256)
k_agg(const float* __restrict__ conv_b, int n) {
    int warp = threadIdx.x >> 5;
    int lane = threadIdx.x & 31;
    int d = blockIdx.x * 8 + warp;
    if (d >= n) return;
    int beg = d_cnt[d], end = d_cnt[d + 1];
    float adstv = (lane < 8) ? d_adst[d * 8 + lane] : 0.f;
    float esum = 0.f;
    float acc[8];
    #pragma unroll
    for (int j = 0; j < 8; j++) acc[j] = 0.f;
    int s = d;
    int p = beg - 1;
    while (true) {
        float av = 0.f;
        if (lane < 8) {
            float lg = lrelu(d_asrc[s * 8 + lane] + adstv, 0.2f);
            av = __expf(lg);
            esum += av;
        }
        const float* xr = d_xp + (size_t)s * 256;
        #pragma unroll
        for (int j = 0; j < 8; j++) {
            float ah = __shfl_sync(0xffffffffu, av, j);
            acc[j] = fmaf(ah, xr[j * 32 + lane], acc[j]);
        }
        p++;
        if (p >= end) break;
        s = d_srcs[p];
    }
    float* outr = d_agg + (size_t)d * 256;
    #pragma unroll
    for (int j = 0; j < 8; j++) {
        float sh = __shfl_sync(0xffffffffu, esum, j);
        outr[j * 32 + lane] = acc[j] / (sh + 1e-16f) + conv_b[j * 32 + lane];
    }
}

// ---------------- dense per-node chain (f32x2) + fused global pooling ----------------
__global__ void __launch_bounds__(256)
k_dense(const float* __restrict__ fc_b,
        const float* __restrict__ ln_w, const float* __restrict__ ln_b,
        const float* __restrict__ gw, const float* __restrict__ gb, int n) {
    __shared__ __align__(16) float vs[16][256];
    __shared__ float sred[16 * 8];
    __shared__ float sbc[16];
    __shared__ float sbc2[16];
    int tid = threadIdx.x;
    int n0 = blockIdx.x * 16;
    float fb = fc_b[tid];
    float lw = ln_w[tid], lb = ln_b[tid];

    #pragma unroll
    for (int m = 0; m < 16; m++) {
        int nn = n0 + m;
        vs[m][tid] = (nn < n) ? d_agg[(size_t)nn * 256 + tid] : 0.f;
    }
    __syncthreads();

    // GEMV1: y = lrelu(v @ fcT + fb, 0.01)   [f32x2 packed]
    unsigned long long c2[16];
    #pragma unroll
    for (int m = 0; m < 16; m++) c2[m] = 0ull;
    #pragma unroll 1
    for (int k4 = 0; k4 < 64; k4++) {
        ulonglong2 w = d_fcTp[k4 * 256 + tid];
        #pragma unroll
        for (int m = 0; m < 16; m++) {
            ulonglong2 a = ((const ulonglong2*)vs[m])[k4];
            fma2(c2[m], a.x, w.x);
            fma2(c2[m], a.y, w.y);
        }
    }
    float acc[16];
    #pragma unroll
    for (int m = 0; m < 16; m++) acc[m] = lrelu(unpack_sum(c2[m]) + fb, 0.01f);

    // row softmax
    reduce16(acc, sred, sbc, true, tid);
    float e[16];
    #pragma unroll
    for (int m = 0; m < 16; m++) e[m] = __expf(acc[m] - sbc[m]);
    reduce16(e, sred, sbc2, false, tid);

    // x2 = lrelu(v * sa, 0.2)
    float x2[16];
    #pragma unroll
    for (int m = 0; m < 16; m++) {
        float sa = e[m] / sbc2[m];
        x2[m] = lrelu(vs[m][tid] * sa, 0.2f);
    }
    __syncthreads();
    #pragma unroll
    for (int m = 0; m < 16; m++) vs[m][tid] = x2[m];
    __syncthreads();

    // GEMV2 [f32x2 packed]
    #pragma unroll
    for (int m = 0; m < 16; m++) c2[m] = 0ull;
    #pragma unroll 1
    for (int k4 = 0; k4 < 64; k4++) {
        ulonglong2 w = d_fcTp[k4 * 256 + tid];
        #pragma unroll
        for (int m = 0; m < 16; m++) {
            ulonglong2 a = ((const ulonglong2*)vs[m])[k4];
            fma2(c2[m], a.x, w.x);
            fma2(c2[m], a.y, w.y);
        }
    }
    #pragma unroll
    for (int m = 0; m < 16; m++) acc[m] = unpack_sum(c2[m]) + fb;

    // LayerNorm
    reduce16(acc, sred, sbc, false, tid);
    float mu[16], sq[16];
    #pragma unroll
    for (int m = 0; m < 16; m++) {
        mu[m] = sbc[m] * (1.f / 256.f);
        float dd = acc[m] - mu[m];
        sq[m] = dd * dd;
    }
    reduce16(sq, sred, sbc2, false, tid);
    float xl[16];
    #pragma unroll
    for (int m = 0; m < 16; m++) {
        float var = sbc2[m] * (1.f / 256.f);
        xl[m] = (acc[m] - mu[m]) * rsqrtf(var + 1e-5f) * lw + lb;
    }

    // L2 normalize
    #pragma unroll
    for (int m = 0; m < 16; m++) sq[m] = xl[m] * xl[m];
    reduce16(sq, sred, sbc, false, tid);
    #pragma unroll
    for (int m = 0; m < 16; m++) xl[m] /= fmaxf(sqrtf(sbc[m]), 1e-12f);

    // gate scalar per node -> sbc2[m]
    float gwt = gw[tid];
    #pragma unroll
    for (int m = 0; m < 16; m++) sq[m] = xl[m] * gwt;
    reduce16(sq, sred, sbc2, false, tid);

    // store x_local + fused global pooling accumulation
    float gb0 = gb[0];
    float pool = 0.f;
    float evsum = 0.f;
    #pragma unroll
    for (int m = 0; m < 16; m++) {
        if (n0 + m < n) {
            d_agg[(size_t)(n0 + m) * 256 + tid] = xl[m];
            float ev = __expf(sbc2[m] + gb0);
            pool += ev * xl[m];
            evsum += ev;
        }
    }
    atomicAdd(&d_xglob[tid], pool);
    if (tid == 0) atomicAdd(&d_gsum, evsum);  // evsum identical across tid (per-m uniform)
}

// ---------------- final ga + output ----------------
__global__ void k_ga(const float* __restrict__ gfcw, const float* __restrict__ gfcb) {
    __shared__ float xg[256];
    __shared__ float r8[8];
    __shared__ float bres;
    int tid = threadIdx.x;
    xg[tid] = d_xglob[tid] / (d_gsum + 1e-16f);
    __syncthreads();
    float acc = gfcb[tid];
    const float* row = gfcw + (size_t)tid * 256;
    #pragma unroll 4
    for (int k = 0; k < 256; k++) acc += xg[k] * row[k];
    acc = fmaxf(acc, 0.f);
    float r = wredmax(acc);
    if ((tid & 31) == 0) r8[tid >> 5] = r;
    __syncthreads();
    if (tid == 0) {
        float m = r8[0];
        #pragma unroll
        for (int j = 1; j < 8; j++) m = fmaxf(m, r8[j]);
        bres = m;
    }
    __syncthreads();
    float e = __expf(acc - bres);
    r = wredsum(e);
    if ((tid & 31) == 0) r8[tid >> 5] = r;
    __syncthreads();
    if (tid == 0) {
        float s = 0.f;
        #pragma unroll
        for (int j = 0; j < 8; j++) s += r8[j];
        bres = s;
    }
    __syncthreads();
    d_ga[tid] = e / bres;
}

__global__ void k_out(float* __restrict__ out, int n) {
    int idx = blockIdx.x * blockDim.x + threadIdx.x;
    if (idx >= n * 64) return;
    int o4 = idx & 63;
    float4 g = ((const float4*)d_ga)[o4];
    float4 v = ((const float4*)d_agg)[idx];
    v.x *= g.x; v.y *= g.y; v.z *= g.z; v.w *= g.w;
    ((float4*)out)[idx] = v;
}

// ---------------- launch ----------------
extern "C" void kernel_launch(void* const* d_in, const int* in_sizes, int n_in,
                              void* d_out, int out_size) {
    const float* x      = (const float*)d_in[0];
    const int*   ei     = (const int*)  d_in[1];
    const float* W      = (const float*)d_in[4];
    const float* a_src  = (const float*)d_in[5];
    const float* a_dst  = (const float*)d_in[6];
    const float* conv_b = (const float*)d_in[7];
    const float* fc_w   = (const float*)d_in[8];
    const float* fc_b   = (const float*)d_in[9];
    const float* ln_w   = (const float*)d_in[10];
    const float* ln_b   = (const float*)d_in[11];
    const float* gate_w = (const float*)d_in[12];
    const float* gate_b = (const float*)d_in[13];
    const float* gfc_w  = (const float*)d_in[14];
    const float* gfc_b  = (const float*)d_in[15];
    float* out = (float*)d_out;

    int n = in_sizes[0] / 128;
    int E = in_sizes[1] / 2;
    int nb = (n + 1023) / 1024;

    k_init<<<(n + 256) / 256, 256>>>(n);
    k_fcT<<<256, 256>>>(fc_w);
    k_wp<<<128, 256>>>(W);
    k_hist<<<(E + 255) / 256, 256>>>(ei, E);
    k_scan1<<<nb, 1024>>>(n);
    k_scan2<<<1, 32>>>(nb);
    k_scan3<<<nb, 1024>>>(n, E);
    k_scatter<<<(E + 255) / 256, 256>>>(ei, E);
    k_xp<<<(n + 7) / 8, 256>>>(x, a_src, a_dst, n);
    k_agg<<<(n + 7) / 8, 256>>>(conv_b, n);
    k_dense<<<(n + 15) / 16, 256>>>(fc_b, ln_w, ln_b, gate_w, gate_b, n);
    k_ga<<<1, 256>>>(gfc_w, gfc_b);
    k_out<<<(n * 64 + 255) / 256, 256>>>(out, n);
}

// round 15
// speedup vs baseline: 3.3312x; 1.0547x over previous
#include <cuda_runtime.h>
#include <cuda_bf16.h>
#include <stdint.h>
#include <math.h>

#define NMAX 30000
#define EMAX 600000

// ---------------- scratch ----------------
__device__ float      d_xp  [NMAX * 256];
__device__ float      d_agg [NMAX * 256];
__device__ float      d_asrc[NMAX * 8];
__device__ float      d_adst[NMAX * 8];
__device__ ulonglong2 d_fcTp[64 * 256];    // fc_w^T packed: [k4][o] = 4 floats {w[4k4..4k4+3][o]}
__device__ ulonglong2 d_Wp  [8 * 32 * 32]; // W packed: [h][i4][d] = 4 floats {W[h][4i4..4i4+3][d]}
__device__ float      d_gsum;
__device__ float      d_xglob[256];
__device__ float      d_ga[256];
__device__ int        d_cnt[NMAX + 1];
__device__ int        d_cur[NMAX];
__device__ int        d_srcs[EMAX];
__device__ int        d_bsum[64];

// ---------------- helpers ----------------
__device__ __forceinline__ float lrelu(float x, float s) { return x > 0.f ? x : s * x; }

__device__ __forceinline__ float wredsum(float v) {
    #pragma unroll
    for (int s = 16; s; s >>= 1) v += __shfl_xor_sync(0xffffffffu, v, s);
    return v;
}
__device__ __forceinline__ float wredmax(float v) {
    #pragma unroll
    for (int s = 16; s; s >>= 1) v = fmaxf(v, __shfl_xor_sync(0xffffffffu, v, s));
    return v;
}

// packed f32x2 FMA: c = a*b + c
__device__ __forceinline__ void fma2(unsigned long long& c, unsigned long long a,
                                     unsigned long long b) {
    asm("fma.rn.f32x2 %0, %1, %2, %0;" : "+l"(c) : "l"(a), "l"(b));
}
__device__ __forceinline__ float unpack_sum(unsigned long long p) {
    float lo, hi;
    asm("mov.b64 {%0,%1}, %2;" : "=f"(lo), "=f"(hi) : "l"(p));
    return lo + hi;
}
__device__ __forceinline__ unsigned long long pack2(float lo, float hi) {
    unsigned long long r;
    asm("mov.b64 %0, {%1,%2};" : "=l"(r) : "f"(lo), "f"(hi));
    return r;
}
__device__ __forceinline__ void unpack2(unsigned long long p, float& lo, float& hi) {
    asm("mov.b64 {%0,%1}, %2;" : "=f"(lo), "=f"(hi) : "l"(p));
}

// block reduce of 16 per-thread values over 256 threads
__device__ __forceinline__ void reduce16(const float* v, float* sred, float* out,
                                         bool ismax, int tid) {
    int wid = tid >> 5, lane = tid & 31;
    #pragma unroll
    for (int m = 0; m < 16; m++) {
        float r = ismax ? wredmax(v[m]) : wredsum(v[m]);
        if (lane == 0) sred[m * 8 + wid] = r;
    }
    __syncthreads();
    if (tid < 16) {
        float r = sred[tid * 8];
        #pragma unroll
        for (int j = 1; j < 8; j++) {
            float t = sred[tid * 8 + j];
            r = ismax ? fmaxf(r, t) : r + t;
        }
        out[tid] = r;
    }
    __syncthreads();
}

// ---------------- setup ----------------
__global__ void k_init(int n) {
    int idx = blockIdx.x * blockDim.x + threadIdx.x;
    if (idx <= n) d_cnt[idx] = 0;
    if (idx < 256) d_xglob[idx] = 0.f;
    if (idx == 0) d_gsum = 0.f;
}

__global__ void k_fcT(const float* __restrict__ fc) {
    int idx = blockIdx.x * blockDim.x + threadIdx.x;  // 65536; fc[o][k]
    int o = idx >> 8, k = idx & 255;
    ((float*)d_fcTp)[(k >> 2) * 1024 + o * 4 + (k & 3)] = fc[idx];
}

__global__ void k_wp(const float* __restrict__ W) {
    int idx = blockIdx.x * blockDim.x + threadIdx.x;  // 32768 = h*4096 + i*32 + d
    int h = idx >> 12, i = (idx >> 5) & 127, d = idx & 31;
    ((float*)d_Wp)[(((h * 32) + (i >> 2)) * 32 + d) * 4 + (i & 3)] = W[idx];
}

// ---------------- CSR build (proven) ----------------
__global__ void k_hist(const int* __restrict__ ei, int E) {
    int e = blockIdx.x * blockDim.x + threadIdx.x;
    if (e < E) atomicAdd(&d_cnt[ei[E + e]], 1);
}
__global__ void k_scan1(int n) {
    __shared__ int sh[1024];
    int b = blockIdx.x, t = threadIdx.x;
    int i = b * 1024 + t;
    int v = (i < n) ? d_cnt[i] : 0;
    sh[t] = v;
    __syncthreads();
    #pragma unroll
    for (int off = 1; off < 1024; off <<= 1) {
        int x = (t >= off) ? sh[t - off] : 0;
        __syncthreads();
        sh[t] += x;
        __syncthreads();
    }
    if (i < n) d_cur[i] = sh[t] - v;
    if (t == 1023) d_bsum[b] = sh[1023];
}
__global__ void k_scan2(int nb) {
    int t = threadIdx.x;
    int v = (t < nb) ? d_bsum[t] : 0;
    int orig = v;
    #pragma unroll
    for (int off = 1; off < 32; off <<= 1) {
        int x = __shfl_up_sync(0xffffffffu, v, off);
        if (t >= off) v += x;
    }
    if (t < nb) d_bsum[t] = v - orig;
}
__global__ void k_scan3(int n, int E) {
    int b = blockIdx.x, t = threadIdx.x;
    int i = b * 1024 + t;
    if (i < n) {
        int v = d_cur[i] + d_bsum[b];
        d_cnt[i] = v;
        d_cur[i] = v;
    }
    if (i == 0) d_cnt[n] = E;
}
__global__ void k_scatter(const int* __restrict__ ei, int E) {
    int e = blockIdx.x * blockDim.x + threadIdx.x;
    if (e >= E) return;
    int d = ei[E + e];
    int pos = atomicAdd(&d_cur[d], 1);
    d_srcs[pos] = ei[e];
}

// ---------------- xp + alpha (f32x2 inner loop, proven) ----------------
__global__ void __launch_bounds__(256)
k_xp(const float* __restrict__ x,
     const float* __restrict__ a_src, const float* __restrict__ a_dst, int n) {
    __shared__ __align__(16) float xs[8][128];
    int tid = threadIdx.x;
    int n0 = blockIdx.x * 8;
    for (int idx = tid; idx < 8 * 128; idx += 256) {
        int m = idx >> 7, i = idx & 127;
        int nn = n0 + m;
        xs[m][i] = (nn < n) ? x[(size_t)nn * 128 + i] : 0.f;
    }
    __syncthreads();

    int h = tid >> 5, d = tid & 31;
    unsigned long long acc2[8];
    #pragma unroll
    for (int m = 0; m < 8; m++) acc2[m] = 0ull;
    const ulonglong2* Wp = d_Wp + (size_t)h * 32 * 32 + d;
    #pragma unroll 1
    for (int i4 = 0; i4 < 32; i4++) {
        ulonglong2 wv = Wp[i4 * 32];
        #pragma unroll
        for (int m = 0; m < 8; m++) {
            ulonglong2 xv = ((const ulonglong2*)xs[m])[i4];
            fma2(acc2[m], xv.x, wv.x);
            fma2(acc2[m], xv.y, wv.y);
        }
    }

    float asv = a_src[h * 32 + d];
    float adv = a_dst[h * 32 + d];
    int lane = tid & 31;
    #pragma unroll
    for (int m = 0; m < 8; m++) {
        float acc = unpack_sum(acc2[m]);
        int nn = n0 + m;
        float rs = wredsum(acc * asv);
        float rd = wredsum(acc * adv);
        if (nn < n) {
            d_xp[(size_t)nn * 256 + tid] = acc;
            if (lane == 0) {
                d_asrc[nn * 8 + h] = rs;
                d_adst[nn * 8 + h] = rd;
            }
        }
    }
}

// ---------------- fused attention aggregation (+conv_b) ----------------
// Packed 128-bit gathers + f32x2 FMA + software-pipelined prefetch.
// Element mapping per lane L: chunk c in {0,1} covers row floats [c*128 + 4L .. +3];
// head of that 16B chunk = 4c + (L>>3) (uniform within chunk).
__global__ void __launch_bounds__(256)
k_agg(const float* __restrict__ conv_b, int n) {
    int warp = threadIdx.x >> 5;
    int lane = threadIdx.x & 31;
    int d = blockIdx.x * 8 + warp;
    if (d >= n) return;
    int beg = d_cnt[d], end = d_cnt[d + 1];
    float adstv = (lane < 8) ? d_adst[d * 8 + lane] : 0.f;
    float esum = 0.f;
    unsigned long long acc2[4] = {0ull, 0ull, 0ull, 0ull};

    // pipeline state: current src row pre-loaded (self loop first)
    int s_cur = d;
    const ulonglong2* xr = (const ulonglong2*)(d_xp + (size_t)s_cur * 256);
    ulonglong2 r0 = xr[lane];
    ulonglong2 r1 = xr[32 + lane];
    float as_cur = (lane < 8) ? d_asrc[s_cur * 8 + lane] : 0.f;
    int p = beg;

    while (true) {
        // prefetch next src row while computing current
        int s_nxt = (p < end) ? d_srcs[p] : -1;
        ulonglong2 n0, n1;
        float as_nxt = 0.f;
        if (s_nxt >= 0) {
            const ulonglong2* xn = (const ulonglong2*)(d_xp + (size_t)s_nxt * 256);
            n0 = xn[lane];
            n1 = xn[32 + lane];
            if (lane < 8) as_nxt = d_asrc[s_nxt * 8 + lane];
        }
        // attention weight for current src (lanes 0-7 hold per-head values)
        float av = 0.f;
        if (lane < 8) {
            av = __expf(lrelu(as_cur + adstv, 0.2f));
            esum += av;
        }
        float ah0 = __shfl_sync(0xffffffffu, av, lane >> 3);
        float ah1 = __shfl_sync(0xffffffffu, av, 4 + (lane >> 3));
        unsigned long long a0 = pack2(ah0, ah0);
        unsigned long long a1 = pack2(ah1, ah1);
        fma2(acc2[0], r0.x, a0);
        fma2(acc2[1], r0.y, a0);
        fma2(acc2[2], r1.x, a1);
        fma2(acc2[3], r1.y, a1);
        if (s_nxt < 0) break;
        s_cur = s_nxt;
        r0 = n0;
        r1 = n1;
        as_cur = as_nxt;
        p++;
    }

    float sh0 = __shfl_sync(0xffffffffu, esum, lane >> 3);
    float sh1 = __shfl_sync(0xffffffffu, esum, 4 + (lane >> 3));
    float i0 = 1.f / (sh0 + 1e-16f);
    float i1 = 1.f / (sh1 + 1e-16f);
    float* outr = d_agg + (size_t)d * 256;
    float4 cb0 = ((const float4*)conv_b)[lane];
    float4 cb1 = ((const float4*)conv_b)[32 + lane];
    float lo, hi;
    float4 o0, o1;
    unpack2(acc2[0], lo, hi); o0.x = lo * i0 + cb0.x; o0.y = hi * i0 + cb0.y;
    unpack2(acc2[1], lo, hi); o0.z = lo * i0 + cb0.z; o0.w = hi * i0 + cb0.w;
    unpack2(acc2[2], lo, hi); o1.x = lo * i1 + cb1.x; o1.y = hi * i1 + cb1.y;
    unpack2(acc2[3], lo, hi); o1.z = lo * i1 + cb1.z; o1.w = hi * i1 + cb1.w;
    ((float4*)outr)[lane] = o0;
    ((float4*)outr)[32 + lane] = o1;
}

// ---------------- dense per-node chain (f32x2) + fused global pooling (proven) ----------------
__global__ void __launch_bounds__(256)
k_dense(const float* __restrict__ fc_b,
        const float* __restrict__ ln_w, const float* __restrict__ ln_b,
        const float* __restrict__ gw, const float* __restrict__ gb, int n) {
    __shared__ __align__(16) float vs[16][256];
    __shared__ float sred[16 * 8];
    __shared__ float sbc[16];
    __shared__ float sbc2[16];
    int tid = threadIdx.x;
    int n0 = blockIdx.x * 16;
    float fb = fc_b[tid];
    float lw = ln_w[tid], lb = ln_b[tid];

    #pragma unroll
    for (int m = 0; m < 16; m++) {
        int nn = n0 + m;
        vs[m][tid] = (nn < n) ? d_agg[(size_t)nn * 256 + tid] : 0.f;
    }
    __syncthreads();

    unsigned long long c2[16];
    #pragma unroll
    for (int m = 0; m < 16; m++) c2[m] = 0ull;
    #pragma unroll 1
    for (int k4 = 0; k4 < 64; k4++) {
        ulonglong2 w = d_fcTp[k4 * 256 + tid];
        #pragma unroll
        for (int m = 0; m < 16; m++) {
            ulonglong2 a = ((const ulonglong2*)vs[m])[k4];
            fma2(c2[m], a.x, w.x);
            fma2(c2[m], a.y, w.y);
        }
    }
    float acc[16];
    #pragma unroll
    for (int m = 0; m < 16; m++) acc[m] = lrelu(unpack_sum(c2[m]) + fb, 0.01f);

    reduce16(acc, sred, sbc, true, tid);
    float e[16];
    #pragma unroll
    for (int m = 0; m < 16; m++) e[m] = __expf(acc[m] - sbc[m]);
    reduce16(e, sred, sbc2, false, tid);

    float x2[16];
    #pragma unroll
    for (int m = 0; m < 16; m++) {
        float sa = e[m] / sbc2[m];
        x2[m] = lrelu(vs[m][tid] * sa, 0.2f);
    }
    __syncthreads();
    #pragma unroll
    for (int m = 0; m < 16; m++) vs[m][tid] = x2[m];
    __syncthreads();

    #pragma unroll
    for (int m = 0; m < 16; m++) c2[m] = 0ull;
    #pragma unroll 1
    for (int k4 = 0; k4 < 64; k4++) {
        ulonglong2 w = d_fcTp[k4 * 256 + tid];
        #pragma unroll
        for (int m = 0; m < 16; m++) {
            ulonglong2 a = ((const ulonglong2*)vs[m])[k4];
            fma2(c2[m], a.x, w.x);
            fma2(c2[m], a.y, w.y);
        }
    }
    #pragma unroll
    for (int m = 0; m < 16; m++) acc[m] = unpack_sum(c2[m]) + fb;

    reduce16(acc, sred, sbc, false, tid);
    float mu[16], sq[16];
    #pragma unroll
    for (int m = 0; m < 16; m++) {
        mu[m] = sbc[m] * (1.f / 256.f);
        float dd = acc[m] - mu[m];
        sq[m] = dd * dd;
    }
    reduce16(sq, sred, sbc2, false, tid);
    float xl[16];
    #pragma unroll
    for (int m = 0; m < 16; m++) {
        float var = sbc2[m] * (1.f / 256.f);
        xl[m] = (acc[m] - mu[m]) * rsqrtf(var + 1e-5f) * lw + lb;
    }

    #pragma unroll
    for (int m = 0; m < 16; m++) sq[m] = xl[m] * xl[m];
    reduce16(sq, sred, sbc, false, tid);
    #pragma unroll
    for (int m = 0; m < 16; m++) xl[m] /= fmaxf(sqrtf(sbc[m]), 1e-12f);

    float gwt = gw[tid];
    #pragma unroll
    for (int m = 0; m < 16; m++) sq[m] = xl[m] * gwt;
    reduce16(sq, sred, sbc2, false, tid);

    float gb0 = gb[0];
    float pool = 0.f;
    float evsum = 0.f;
    #pragma unroll
    for (int m = 0; m < 16; m++) {
        if (n0 + m < n) {
            d_agg[(size_t)(n0 + m) * 256 + tid] = xl[m];
            float ev = __expf(sbc2[m] + gb0);
            pool += ev * xl[m];
            evsum += ev;
        }
    }
    atomicAdd(&d_xglob[tid], pool);
    if (tid == 0) atomicAdd(&d_gsum, evsum);
}

// ---------------- final ga + output ----------------
__global__ void k_ga(const float* __restrict__ gfcw, const float* __restrict__ gfcb) {
    __shared__ float xg[256];
    __shared__ float r8[8];
    __shared__ float bres;
    int tid = threadIdx.x;
    xg[tid] = d_xglob[tid] / (d_gsum + 1e-16f);
    __syncthreads();
    float acc = gfcb[tid];
    const float* row = gfcw + (size_t)tid * 256;
    #pragma unroll 4
    for (int k = 0; k < 256; k++) acc += xg[k] * row[k];
    acc = fmaxf(acc, 0.f);
    float r = wredmax(acc);
    if ((tid & 31) == 0) r8[tid >> 5] = r;
    __syncthreads();
    if (tid == 0) {
        float m = r8[0];
        #pragma unroll
        for (int j = 1; j < 8; j++) m = fmaxf(m, r8[j]);
        bres = m;
    }
    __syncthreads();
    float e = __expf(acc - bres);
    r = wredsum(e);
    if ((tid & 31) == 0) r8[tid >> 5] = r;
    __syncthreads();
    if (tid == 0) {
        float s = 0.f;
        #pragma unroll
        for (int j = 0; j < 8; j++) s += r8[j];
        bres = s;
    }
    __syncthreads();
    d_ga[tid] = e / bres;
}

__global__ void k_out(float* __restrict__ out, int n) {
    int idx = blockIdx.x * blockDim.x + threadIdx.x;
    if (idx >= n * 64) return;
    int o4 = idx & 63;
    float4 g = ((const float4*)d_ga)[o4];
    float4 v = ((const float4*)d_agg)[idx];
    v.x *= g.x; v.y *= g.y; v.z *= g.z; v.w *= g.w;
    ((float4*)out)[idx] = v;
}

// ---------------- launch ----------------
extern "C" void kernel_launch(void* const* d_in, const int* in_sizes, int n_in,
                              void* d_out, int out_size) {
    const float* x      = (const float*)d_in[0];
    const int*   ei     = (const int*)  d_in[1];
    const float* W      = (const float*)d_in[4];
    const float* a_src  = (const float*)d_in[5];
    const float* a_dst  = (const float*)d_in[6];
    const float* conv_b = (const float*)d_in[7];
    const float* fc_w   = (const float*)d_in[8];
    const float* fc_b   = (const float*)d_in[9];
    const float* ln_w   = (const float*)d_in[10];
    const float* ln_b   = (const float*)d_in[11];
    const float* gate_w = (const float*)d_in[12];
    const float* gate_b = (const float*)d_in[13];
    const float* gfc_w  = (const float*)d_in[14];
    const float* gfc_b  = (const float*)d_in[15];
    float* out = (float*)d_out;

    int n = in_sizes[0] / 128;
    int E = in_sizes[1] / 2;
    int nb = (n + 1023) / 1024;

    k_init<<<(n + 256) / 256, 256>>>(n);
    k_fcT<<<256, 256>>>(fc_w);
    k_wp<<<128, 256>>>(W);
    k_hist<<<(E + 255) / 256, 256>>>(ei, E);
    k_scan1<<<nb, 1024>>>(n);
    k_scan2<<<1, 32>>>(nb);
    k_scan3<<<nb, 1024>>>(n, E);
    k_scatter<<<(E + 255) / 256, 256>>>(ei, E);
    k_xp<<<(n + 7) / 8, 256>>>(x, a_src, a_dst, n);
    k_agg<<<(n + 7) / 8, 256>>>(conv_b, n);
    k_dense<<<(n + 15) / 16, 256>>>(fc_b, ln_w, ln_b, gate_w, gate_b, n);
    k_ga<<<1, 256>>>(gfc_w, gfc_b);
    k_out<<<(n * 64 + 255) / 256, 256>>>(out, n);
}